// round 17
// baseline (speedup 1.0000x reference)
#include <cuda_runtime.h>
#include <cuda_bf16.h>
#include <cstdint>

#define NREG     10000
#define NBINS    32
#define NBUCKETS 128
#define PTS      4          // points per thread (PTS=8 regressed: regs 56 / occ 41%)

// Scratch (device globals are the sanctioned scratch mechanism).
// Bin struct (16 B): {bl_l, cdf_l, h_l, A = (h_r - h_l)/w}; the bin's own
// index k lives in the low 5 mantissa bits of A (rel perturbation ~2^-18).
__device__ __align__(16) float4 g_bins16[NREG * NBINS];        // 5.12 MB
// Bucket-direct table: bucket b holds the struct of the UPPER-BOUND bin for
// x in [b/128, (b+1)/128) (k packed the same way).
__device__ __align__(16) float4 g_buckets[NREG * NBUCKETS];    // 20.48 MB

// ---------------------------------------------------------------------------
// Kernel 1: one warp per region, fully register-resident. EVERY thread
// executes the PDL trigger on the common exit path, AFTER the table stores:
// the dependent grid's cudaGridDependencySynchronize() then guarantees
// visibility of all table writes (no reliance on implicit trigger-on-exit,
// no trigger-before-stores race).
// ---------------------------------------------------------------------------
__global__ void __launch_bounds__(256)
spline_prep_kernel(const float* __restrict__ uw, const float* __restrict__ uh)
{
    const int warp = threadIdx.x >> 5;
    const int lane = threadIdx.x & 31;
    const int r    = blockIdx.x * 8 + warp;

    if (r < NREG) {
        const float w_logit = uw[r * NBINS + lane];
        const float h_logit = uh[r * (NBINS + 1) + lane];
        const float h_last  = uh[r * (NBINS + 1) + NBINS];

        // --- softmax over widths ---
        float m = w_logit;
        #pragma unroll
        for (int o = 16; o; o >>= 1) m = fmaxf(m, __shfl_xor_sync(0xffffffffu, m, o));
        float e = __expf(w_logit - m);
        float s = e;
        #pragma unroll
        for (int o = 16; o; o >>= 1) s += __shfl_xor_sync(0xffffffffu, s, o);
        const float w = e / s;

        // --- heights: exp, normalize by trapezoid area ---
        float hexp   = __expf(h_logit);
        float hexp_n = __shfl_down_sync(0xffffffffu, hexp, 1);
        if (lane == 31) hexp_n = __expf(h_last);

        float area = 0.5f * (hexp + hexp_n) * w;
        #pragma unroll
        for (int o = 16; o; o >>= 1) area += __shfl_xor_sync(0xffffffffu, area, o);
        const float inv_area = 1.0f / area;
        const float hl = hexp * inv_area;
        const float hr = hexp_n * inv_area;

        // --- inclusive scans: cdf over trapezoids, locs over widths ---
        float cdf = 0.5f * (hl + hr) * w;
        float loc = w;
        #pragma unroll
        for (int o = 1; o < 32; o <<= 1) {
            const float c = __shfl_up_sync(0xffffffffu, cdf, o);
            const float l = __shfl_up_sync(0xffffffffu, loc, o);
            if (lane >= o) { cdf += c; loc += l; }
        }
        float cdf_l = __shfl_up_sync(0xffffffffu, cdf, 1); if (lane == 0) cdf_l = 0.0f;
        float bl_l  = __shfl_up_sync(0xffffffffu, loc, 1); if (lane == 0) bl_l  = 0.0f;

        // --- per-lane bin struct, k packed into A's low 5 mantissa bits ---
        const float A  = (hr - hl) / w;
        const float Ap = __uint_as_float((__float_as_uint(A) & ~31u) | (unsigned)lane);
        g_bins16[r * NBINS + lane] = make_float4(bl_l, cdf_l, hl, Ap);

        // --- bucket-direct table: k_ub = max k<=31 with bl[k] <= (b+1)/128 ---
        float4* buckets = g_buckets + (size_t)r * NBUCKETS;
        int kj[NBUCKETS / 32];
        #pragma unroll
        for (int j = 0; j < NBUCKETS / 32; j++) {
            const int b   = lane + j * 32;
            const float v = (float)(b + 1) * (1.0f / (float)NBUCKETS);  // exact
            int k = 0;
            #pragma unroll
            for (int st = 16; st >= 1; st >>= 1) {
                const int t = k + st;
                const float blt = __shfl_sync(0xffffffffu, bl_l, t & 31);
                if (t <= 31 && blt <= v) k = t;
            }
            kj[j] = k;
        }
        #pragma unroll
        for (int j = 0; j < NBUCKETS / 32; j++) {
            const int k = kj[j];
            const float e0 = __shfl_sync(0xffffffffu, bl_l,  k);
            const float e1 = __shfl_sync(0xffffffffu, cdf_l, k);
            const float e2 = __shfl_sync(0xffffffffu, hl,    k);
            const float e3 = __shfl_sync(0xffffffffu, Ap,    k);
            buckets[lane + j * 32] = make_float4(e0, e1, e2, e3);   // coalesced
        }
    }

    // PDL trigger: all threads, after all stores.
#if __CUDA_ARCH__ >= 900
    cudaTriggerProgrammaticLaunchCompletion();
#endif
}

// ---------------------------------------------------------------------------
// Kernel 2: R9 best-measured shape + PDL. Prelude (x/ix loads, bucket address
// math) runs BEFORE cudaGridDependencySynchronize, overlapping prep's drain /
// teardown.
// ---------------------------------------------------------------------------
__global__ void __launch_bounds__(256)
spline_eval_kernel(const float* __restrict__ x, const int* __restrict__ ix,
                   float* __restrict__ out, float* __restrict__ lad, int n)
{
    const int i0 = (blockIdx.x * blockDim.x + threadIdx.x) * PTS;

    float xs[PTS];
    const float4* ga[PTS];
    int rs[PTS];
    if (i0 < n) {   // n % 4 == 0
        const float4 xv = *reinterpret_cast<const float4*>(x + i0);
        const int4   rv = *reinterpret_cast<const int4*>(ix + i0);
        xs[0] = xv.x; xs[1] = xv.y; xs[2] = xv.z; xs[3] = xv.w;
        rs[0] = rv.x; rs[1] = rv.y; rs[2] = rv.z; rs[3] = rv.w;
        #pragma unroll
        for (int j = 0; j < PTS; j++) {
            const int b = min((int)(xs[j] * (float)NBUCKETS), NBUCKETS - 1);
            ga[j] = g_buckets + (size_t)rs[j] * NBUCKETS + b;
        }
    }

    // Wait for prep's table writes to be visible (PDL dependency point).
#if __CUDA_ARCH__ >= 900
    cudaGridDependencySynchronize();
#endif
    if (i0 >= n) return;

    // Stage 1: 4 independent bucket loads
    float4 e[PTS];
    #pragma unroll
    for (int j = 0; j < PTS; j++) e[j] = __ldg(ga[j]);

    // Stage 2 pass 1: predecessor loads for all fallback slots, issued
    // back-to-back (each depends only on its own stage-1 result).
    // bin0 has bl_l = 0, so x < bl_l implies k_ub >= 1.
    #pragma unroll
    for (int j = 0; j < PTS; j++) {
        if (xs[j] < e[j].x)
            e[j] = __ldg(g_bins16 + (size_t)rs[j] * NBINS
                         + ((int)(__float_as_uint(e[j].w) & 31u) - 1));
    }

    // Stage 2 pass 2: rare serial walk (bucket with >=2 interior boundaries).
    #pragma unroll
    for (int j = 0; j < PTS; j++) {
        if (xs[j] < e[j].x) {                          // ~0.9% of points
            int k = (int)(__float_as_uint(e[j].w) & 31u);
            do {
                k--;
                e[j] = __ldg(g_bins16 + (size_t)rs[j] * NBINS + k);
            } while (k > 0 && xs[j] < e[j].x);
        }
    }

    // Compute + store: out = cdf_l + t*(h_l + 0.5*A*t);  lad = log(h_l + A*t)
    float o[PTS], l[PTS];
    #pragma unroll
    for (int j = 0; j < PTS; j++) {
        const float t = xs[j] - e[j].x;
        o[j] = fmaf(t, fmaf(0.5f * e[j].w, t, e[j].z), e[j].y);
        l[j] = __logf(fmaf(e[j].w, t, e[j].z));
    }
    *reinterpret_cast<float4*>(out + i0) = make_float4(o[0], o[1], o[2], o[3]);
    *reinterpret_cast<float4*>(lad + i0) = make_float4(l[0], l[1], l[2], l[3]);
}

// ---------------------------------------------------------------------------
extern "C" void kernel_launch(void* const* d_in, const int* in_sizes, int n_in,
                              void* d_out, int out_size)
{
    const float* x  = (const float*)d_in[0];
    const int*   ix = (const int*)d_in[1];
    const float* uw = (const float*)d_in[2];
    const float* uh = (const float*)d_in[3];

    const int n = in_sizes[0];                   // 2,000,000 points
    float* out = (float*)d_out;                  // outputs[0:n]
    float* lad = (float*)d_out + n;              // logabsdet[n:2n]

    const int prep_blocks = (NREG + 7) / 8;
    spline_prep_kernel<<<prep_blocks, 256>>>(uw, uh);

    const int threads = 256;
    const int per_block = threads * PTS;
    const int eval_blocks = (n + per_block - 1) / per_block;

    // PDL launch: eval may begin its prelude while prep drains;
    // cudaGridDependencySynchronize() inside eval provides the real barrier.
    cudaLaunchConfig_t cfg = {};
    cfg.gridDim  = dim3((unsigned)eval_blocks, 1, 1);
    cfg.blockDim = dim3((unsigned)threads, 1, 1);
    cfg.dynamicSmemBytes = 0;
    cfg.stream = 0;   // legacy default stream (same one the harness captures)
    cudaLaunchAttribute attrs[1];
    attrs[0].id = cudaLaunchAttributeProgrammaticStreamSerialization;
    attrs[0].val.programmaticStreamSerializationAllowed = 1;
    cfg.attrs = attrs;
    cfg.numAttrs = 1;
    cudaLaunchKernelEx(&cfg, spline_eval_kernel, x, ix, out, lad, n);
}